// round 6
// baseline (speedup 1.0000x reference)
#include <cuda_runtime.h>
#include <cstdint>

// Problem constants (fixed shapes):
//   B=128, T=2048, F_IN=32, R=256, H=256, F_OUT=32, future_n=64
//   total tokens N = 128 * (2048+64) = 270336
#define NTOTAL 270336
#define TTOT   2112
#define TIN    2048
#define NTILES (NTOTAL / 64)   // 4224

// Fused weights:  M = W_ih @ enc_W  ->  gates[n] = x[n] @ M^T + fused_bias
// f-gate dropped (c0 == 0). Layout [k][hj] (k-major).
__device__ float g_Mi[32 * 256];
__device__ float g_Mg[32 * 256];
__device__ float g_Mo[32 * 256];
__device__ float g_bi[256];
__device__ float g_bg[256];
__device__ float g_bo[256];

// ---- packed f32x2 helpers (sm_103a; PTX-only, ptxas won't auto-fuse) ----
typedef unsigned long long u64t;
__device__ __forceinline__ void ffma2(u64t& d, u64t a, u64t b) {
    asm("fma.rn.f32x2 %0, %1, %2, %0;" : "+l"(d) : "l"(a), "l"(b));
}
__device__ __forceinline__ u64t pack2(float x, float y) {
    u64t r; asm("mov.b64 %0, {%1,%2};" : "=l"(r) : "f"(x), "f"(y)); return r;
}
__device__ __forceinline__ void unpack2(float& lo, float& hi, u64t v) {
    asm("mov.b64 {%0,%1}, %2;" : "=f"(lo), "=f"(hi) : "l"(v));
}
// MUFU.TANH-based activations (validated rel_err ~5e-6)
__device__ __forceinline__ float tanh_a(float v) {
    float r; asm("tanh.approx.f32 %0, %1;" : "=f"(r) : "f"(v)); return r;
}
__device__ __forceinline__ float sig_a(float v) {
    return fmaf(0.5f, tanh_a(0.5f * v), 0.5f);
}

// ---------------------------------------------------------------------------
// K1: fold encoder into LSTM input weights. 99 blocks x 256 threads;
// one warp per M row (W_ih row staged in smem slice, one k per lane).
// Warps 768..791 compute the 768 fused biases (one per lane).
// ---------------------------------------------------------------------------
__global__ __launch_bounds__(256)
void prep_kernel(const float* __restrict__ Wih,
                 const float* __restrict__ encW,
                 const float* __restrict__ encb,
                 const float* __restrict__ bih,
                 const float* __restrict__ bhh) {
    __shared__ float wr_s[8][256];
    int w    = threadIdx.x >> 5;
    int lane = threadIdx.x & 31;
    int gw   = blockIdx.x * 8 + w;          // 0..791
    if (gw < 768) {                         // M rows: 3 planes * 256 hj
        int p  = gw >> 8;
        int hj = gw & 255;
        int row = hj + (p == 0 ? 0 : (p == 1 ? 512 : 768));
        const float* wr = Wih + row * 256;
        #pragma unroll
        for (int i = 0; i < 8; i++) wr_s[w][lane + 32 * i] = wr[lane + 32 * i];
        __syncwarp();
        int k = lane;
        float s = 0.0f;
        #pragma unroll 8
        for (int r = 0; r < 256; r++) s += wr_s[w][r] * encW[r * 32 + k];
        float* dst = (p == 0) ? g_Mi : (p == 1 ? g_Mg : g_Mo);
        dst[k * 256 + hj] = s;
    } else {                                // biases: 24 warps * 32 lanes
        int q = (gw - 768) * 32 + lane;     // 0..767
        int p  = q >> 8;
        int hj = q & 255;
        int row = hj + (p == 0 ? 0 : (p == 1 ? 512 : 768));
        const float* wr = Wih + row * 256;
        float s = 0.0f;
        #pragma unroll 8
        for (int r = 0; r < 256; r++) s += wr[r] * encb[r];
        float* dst = (p == 0) ? g_bi : (p == 1 ? g_bg : g_bo);
        dst[hj] = s + bih[row] + bhh[row];
    }
}

// ---------------------------------------------------------------------------
// K_init: out[n][o] = dec_b[o]   (REDG partials accumulate on top)
// ---------------------------------------------------------------------------
__global__ void init_out_kernel(const float* __restrict__ decb,
                                float* __restrict__ out) {
    int idx = blockIdx.x * blockDim.x + threadIdx.x;   // float4 index
    float4 v = *(const float4*)&decb[(idx & 7) * 4];
    ((float4*)out)[idx] = v;
}

// ---------------------------------------------------------------------------
// K2: fused gates GEMM (K=32) + LSTM elementwise + partial decoder.
// Grid: (4 hj-slices of 64, 74 strips). Block = 256 threads, occ 2.
// Gates thread tile: 8 tok x 2 hj x 3 gates (24 packed f32x2 accumulators).
//   warp == token-group -> X smem loads are full warp-broadcast (1 wf);
//   M loads are LDS.64, amortized over 8 tokens  => FMA-bound, not LDS-bound.
// Then h-tile [64x64] -> smem, partial decode out += h @ dec_W_sliceT
// (2 tok x 4 o per thread, K=64, f32x2 along o) via atomicAdd (REDG).
// ---------------------------------------------------------------------------
__global__ __launch_bounds__(256, 2)
void fused_kernel(const float* __restrict__ x,
                  const float* __restrict__ decW,
                  float* __restrict__ out) {
    __shared__ __align__(16) float Mi_s[32 * 64];
    __shared__ __align__(16) float Mg_s[32 * 64];
    __shared__ __align__(16) float Mo_s[32 * 64];
    __shared__ float bi_s[64], bg_s[64], bo_s[64];
    __shared__ __align__(16) float X_s[64 * 36];    // [tok][32], pad 36
    __shared__ __align__(16) float h_s[64 * 68];    // [tok][64], pad 68
    __shared__ __align__(16) float w_s[64 * 36];    // [k(=hj)][32 o], pad 36

    int tid   = threadIdx.x;
    int hbase = blockIdx.x * 64;

    for (int i = tid; i < 2048; i += 256) {
        int k = i >> 6, j = i & 63;
        Mi_s[i] = g_Mi[k * 256 + hbase + j];
        Mg_s[i] = g_Mg[k * 256 + hbase + j];
        Mo_s[i] = g_Mo[k * 256 + hbase + j];
    }
    if (tid < 64) {
        bi_s[tid] = g_bi[hbase + tid];
        bg_s[tid] = g_bg[hbase + tid];
        bo_s[tid] = g_bo[hbase + tid];
    }
    // decoder slice: w_s[k][o] = decW[o][hbase + k]   (transposed store)
    for (int i = tid; i < 2048; i += 256) {
        int o = i & 31, k = i >> 5;
        w_s[k * 36 + o] = decW[o * 256 + hbase + k];
    }

    int hjg  = tid & 31;           // 32 hj-groups of 2
    int tokg = tid >> 5;           // warp id == token-group (8 tokens)
    int hj0  = hjg * 2;
    int tok0 = tokg * 8;
    // decode mapping: 2 tok x 4 o per thread
    int d_o0 = (tid & 7) * 4;
    int d_t0 = (tid >> 3) * 2;

    for (int tile = blockIdx.y; tile < NTILES; tile += gridDim.y) {
        int n0 = tile * 64;
        __syncthreads();
        {   // load X tile [64 tok][32] (t >= 2048 clamps to last input step)
            int tk = tid >> 2, seg = tid & 3;
            int n = n0 + tk;
            int b = n / TTOT;
            int t = n - b * TTOT;
            if (t > TIN - 1) t = TIN - 1;
            const float* src = x + (size_t)(b * TIN + t) * 32 + seg * 8;
            float4 a0 = *(const float4*)src;
            float4 a1 = *(const float4*)(src + 4);
            *(float4*)&X_s[tk * 36 + seg * 8]     = a0;
            *(float4*)&X_s[tk * 36 + seg * 8 + 4] = a1;
        }
        __syncthreads();

        u64t ai[8], ag[8], ao[8];
        #pragma unroll
        for (int j = 0; j < 8; j++) { ai[j] = 0; ag[j] = 0; ao[j] = 0; }

        #pragma unroll
        for (int k4 = 0; k4 < 32; k4 += 4) {
            float4 xv[8];
            #pragma unroll
            for (int j = 0; j < 8; j++)
                xv[j] = *(const float4*)&X_s[(tok0 + j) * 36 + k4];
            #pragma unroll
            for (int kk = 0; kk < 4; kk++) {
                u64t mi = *(const u64t*)&Mi_s[(k4 + kk) * 64 + hj0];
                u64t mg = *(const u64t*)&Mg_s[(k4 + kk) * 64 + hj0];
                u64t mo = *(const u64t*)&Mo_s[(k4 + kk) * 64 + hj0];
                #pragma unroll
                for (int j = 0; j < 8; j++) {
                    float xs = ((const float*)&xv[j])[kk];
                    u64t xx = pack2(xs, xs);
                    ffma2(ai[j], xx, mi);
                    ffma2(ag[j], xx, mg);
                    ffma2(ao[j], xx, mo);
                }
            }
        }

        // LSTM elementwise (c0=0): h = sig(o) * tanh(sig(i) * tanh(g)) -> h_s
        #pragma unroll
        for (int j = 0; j < 8; j++) {
            float i0, i1, g0, g1, o0v, o1v;
            unpack2(i0, i1, ai[j]);
            unpack2(g0, g1, ag[j]);
            unpack2(o0v, o1v, ao[j]);
            i0  += bi_s[hj0];   i1  += bi_s[hj0 + 1];
            g0  += bg_s[hj0];   g1  += bg_s[hj0 + 1];
            o0v += bo_s[hj0];   o1v += bo_s[hj0 + 1];
            float c0v = sig_a(i0) * tanh_a(g0);
            float c1v = sig_a(i1) * tanh_a(g1);
            float h0  = sig_a(o0v) * tanh_a(c0v);
            float h1  = sig_a(o1v) * tanh_a(c1v);
            *(u64t*)&h_s[(tok0 + j) * 68 + hj0] = pack2(h0, h1);
        }
        __syncthreads();

        // Partial decode: out[n0+t][o] += sum_{k<64} h_s[t][k] * w_s[k][o]
        {
            u64t acc[2][2];
            acc[0][0] = 0; acc[0][1] = 0; acc[1][0] = 0; acc[1][1] = 0;
            #pragma unroll 4
            for (int k4 = 0; k4 < 64; k4 += 4) {
                float4 h0 = *(const float4*)&h_s[d_t0 * 68 + k4];
                float4 h1 = *(const float4*)&h_s[(d_t0 + 1) * 68 + k4];
                #pragma unroll
                for (int kk = 0; kk < 4; kk++) {
                    ulonglong2 wv = *(const ulonglong2*)&w_s[(k4 + kk) * 36 + d_o0];
                    float hs0 = ((const float*)&h0)[kk];
                    float hs1 = ((const float*)&h1)[kk];
                    u64t p0 = pack2(hs0, hs0);
                    u64t p1 = pack2(hs1, hs1);
                    ffma2(acc[0][0], p0, wv.x); ffma2(acc[0][1], p0, wv.y);
                    ffma2(acc[1][0], p1, wv.x); ffma2(acc[1][1], p1, wv.y);
                }
            }
            #pragma unroll
            for (int j = 0; j < 2; j++) {
                float* op = &out[(size_t)(n0 + d_t0 + j) * 32 + d_o0];
                float a, b;
                unpack2(a, b, acc[j][0]);
                atomicAdd(op,     a);
                atomicAdd(op + 1, b);
                unpack2(a, b, acc[j][1]);
                atomicAdd(op + 2, a);
                atomicAdd(op + 3, b);
            }
        }
    }
}

// ---------------------------------------------------------------------------
// Inputs (metadata order): input_seq, enc_W, enc_b, W_ih, W_hh, b_ih, b_hh,
//                          dec_W, dec_b, future_n
// W_hh is dead (state never updates from zeros); future_n fixed at 64.
// ---------------------------------------------------------------------------
extern "C" void kernel_launch(void* const* d_in, const int* in_sizes, int n_in,
                              void* d_out, int out_size) {
    (void)in_sizes; (void)n_in; (void)out_size;
    const float* input = (const float*)d_in[0];
    const float* encW  = (const float*)d_in[1];
    const float* encb  = (const float*)d_in[2];
    const float* Wih   = (const float*)d_in[3];
    const float* bih   = (const float*)d_in[5];
    const float* bhh   = (const float*)d_in[6];
    const float* decW  = (const float*)d_in[7];
    const float* decb  = (const float*)d_in[8];
    float* out = (float*)d_out;

    prep_kernel<<<99, 256>>>(Wih, encW, encb, bih, bhh);
    init_out_kernel<<<(NTOTAL * 32 / 4) / 256, 256>>>(decb, out);
    dim3 g2(4, 74);
    fused_kernel<<<g2, 256>>>(input, decW, out);
}

// round 8
// speedup vs baseline: 1.8953x; 1.8953x over previous
#include <cuda_runtime.h>
#include <cuda_fp16.h>
#include <cstdint>
#include <cstring>

// Problem constants (fixed shapes):
//   B=128, T=2048, F_IN=32, R=256, H=256, F_OUT=32, future_n=64
//   total tokens N = 128 * (2048+64) = 270336
#define NTOTAL 270336
#define TTOT   2112
#define TIN    2048
#define NTILE  2112          // 128-token tiles
#define GRID   148

// Fused-weight fp16 hi/lo images (gmem, written by prep):
//   Wg: [768 gate-cols (i:0-255, g:256-511, o:512-767)][32 k]
//   dW: [32 o][256 k]
__device__ unsigned short g_WgH[768 * 32];
__device__ unsigned short g_WgL[768 * 32];
__device__ unsigned short g_dWH[32 * 256];
__device__ unsigned short g_dWL[32 * 256];
__device__ float g_bias[768];

// ---- SMEM layout (bytes). Wg rows padded to 40 halfs (80B, conflict-free
// for ldmatrix); dW stored k-chunked [4][32 o][64k pad 72]. ----
#define WG_H     0            // 768*40*2 = 61440
#define WG_L     61440
#define DW_H     122880       // 128*72*2 = 18432
#define DW_L     141312
#define BIAS_OFF 159744       // 768 f32
#define DECB_OFF 162816       // 32 f32
#define SMEM_TOTAL 162944

__device__ __forceinline__ uint32_t smem_u32(const void* p) {
    uint32_t a;
    asm("{ .reg .u64 t; cvta.to.shared.u64 t, %1; cvt.u32.u64 %0, t; }"
        : "=r"(a) : "l"(p));
    return a;
}
__device__ __forceinline__ void ldsm4(uint32_t& r0, uint32_t& r1,
                                      uint32_t& r2, uint32_t& r3, uint32_t a) {
    asm volatile("ldmatrix.sync.aligned.m8n8.x4.shared.b16 {%0,%1,%2,%3}, [%4];"
                 : "=r"(r0), "=r"(r1), "=r"(r2), "=r"(r3) : "r"(a));
}
__device__ __forceinline__ void mma16816(float* d,
                                         uint32_t a0, uint32_t a1,
                                         uint32_t a2, uint32_t a3,
                                         uint32_t b0, uint32_t b1) {
    asm volatile(
        "mma.sync.aligned.m16n8k16.row.col.f32.f16.f16.f32 "
        "{%0,%1,%2,%3}, {%4,%5,%6,%7}, {%8,%9}, {%0,%1,%2,%3};"
        : "+f"(d[0]), "+f"(d[1]), "+f"(d[2]), "+f"(d[3])
        : "r"(a0), "r"(a1), "r"(a2), "r"(a3), "r"(b0), "r"(b1));
}
// MUFU.TANH activations (validated rel_err ~5e-6 in fp32 rounds)
__device__ __forceinline__ float tanh_a(float v) {
    float r; asm("tanh.approx.f32 %0, %1;" : "=f"(r) : "f"(v)); return r;
}
__device__ __forceinline__ float sig_a(float v) {
    return fmaf(0.5f, tanh_a(0.5f * v), 0.5f);
}
__device__ __forceinline__ float actf(float iv, float gv, float ov) {
    float cc = sig_a(iv) * tanh_a(gv);
    return sig_a(ov) * tanh_a(cc);
}
// fp16 hi/lo split of a float pair -> packed f16x2 regs (lo-half = first arg)
__device__ __forceinline__ void hsplit(float a, float b,
                                       uint32_t& hi, uint32_t& lo) {
    __half2 h = __floats2half2_rn(a, b);
    float2 bk = __half22float2(h);
    __half2 l = __floats2half2_rn(a - bk.x, b - bk.y);
    memcpy(&hi, &h, 4);
    memcpy(&lo, &l, 4);
}

// ---------------------------------------------------------------------------
// K1: fold encoder into LSTM input weights -> fp16 hi/lo images.
//   bid <  768 : fused M row (one k per lane)
//   768..791   : fused biases
//   792..823   : dec_W row (o = bid-792)
// ---------------------------------------------------------------------------
__global__ void prep_kernel(const float* __restrict__ Wih,
                            const float* __restrict__ encW,
                            const float* __restrict__ encb,
                            const float* __restrict__ bih,
                            const float* __restrict__ bhh,
                            const float* __restrict__ decW) {
    __shared__ float wr_s[256];
    int bid = blockIdx.x, lane = threadIdx.x;
    if (bid < 768) {
        int p  = bid >> 8;
        int hj = bid & 255;
        int row = hj + (p == 0 ? 0 : (p == 1 ? 512 : 768));
        const float* wr = Wih + row * 256;
        #pragma unroll
        for (int i = 0; i < 8; i++) wr_s[lane + 32 * i] = wr[lane + 32 * i];
        __syncwarp();
        float s = 0.0f;
        #pragma unroll 8
        for (int r = 0; r < 256; r++) s += wr_s[r] * encW[r * 32 + lane];
        __half hi = __float2half_rn(s);
        __half lo = __float2half_rn(s - __half2float(hi));
        int idx = bid * 32 + lane;          // col*32 + k
        g_WgH[idx] = *(unsigned short*)&hi;
        g_WgL[idx] = *(unsigned short*)&lo;
    } else if (bid < 792) {
        int q = (bid - 768) * 32 + lane;    // 0..767
        int p  = q >> 8;
        int hj = q & 255;
        int row = hj + (p == 0 ? 0 : (p == 1 ? 512 : 768));
        const float* wr = Wih + row * 256;
        float s = 0.0f;
        #pragma unroll 8
        for (int r = 0; r < 256; r++) s += wr[r] * encb[r];
        g_bias[p * 256 + hj] = s + bih[row] + bhh[row];
    } else {
        int o = bid - 792;                  // 0..31
        #pragma unroll
        for (int i = 0; i < 8; i++) {
            int k = lane + 32 * i;
            float v = decW[o * 256 + k];
            __half hi = __float2half_rn(v);
            __half lo = __float2half_rn(v - __half2float(hi));
            g_dWH[o * 256 + k] = *(unsigned short*)&hi;
            g_dWL[o * 256 + k] = *(unsigned short*)&lo;
        }
    }
}

// ---------------------------------------------------------------------------
// K2: persistent fused kernel. 148 CTAs x 256 threads (8 warps), 1 CTA/SM.
// Each warp owns 16 tokens of a 128-token tile, end-to-end, no barriers:
//   x (gmem f32 -> reg fp16 hi/lo A-frags)
//   per 64-col chunk: gates MMA (3-term fp16 split) -> activation in regs
//     -> h repacked as decoder A-frags (same lane layout!) -> decoder MMA
//   epilogue: dacc + dec_b -> STG (no atomics, no h round-trip).
// ---------------------------------------------------------------------------
__global__ __launch_bounds__(256)
void fused_kernel(const float* __restrict__ x,
                  const float* __restrict__ decb,
                  float* __restrict__ out) {
    extern __shared__ char smem[];
    int tid = threadIdx.x, wid = tid >> 5, lane = tid & 31;

    // ---- stage split weights into padded smem ----
    {
        unsigned short* wgH = (unsigned short*)(smem + WG_H);
        unsigned short* wgL = (unsigned short*)(smem + WG_L);
        for (int i = tid; i < 24576; i += 256) {
            int col = i >> 5, k = i & 31;
            wgH[col * 40 + k] = g_WgH[i];
            wgL[col * 40 + k] = g_WgL[i];
        }
        unsigned short* dwH = (unsigned short*)(smem + DW_H);
        unsigned short* dwL = (unsigned short*)(smem + DW_L);
        for (int i = tid; i < 8192; i += 256) {
            int o = i >> 8, k = i & 255;
            int row = (k >> 6) * 32 + o, ck = k & 63;
            dwH[row * 72 + ck] = g_dWH[i];
            dwL[row * 72 + ck] = g_dWL[i];
        }
        float* bs = (float*)(smem + BIAS_OFF);
        for (int i = tid; i < 768; i += 256) bs[i] = g_bias[i];
        if (tid < 32) ((float*)(smem + DECB_OFF))[tid] = decb[tid];
    }
    __syncthreads();

    uint32_t sb = smem_u32(smem);
    const float* bias_s = (const float*)(smem + BIAS_OFF);
    const float* decb_s = (const float*)(smem + DECB_OFF);

    // ldmatrix lane geometry: j = lane/8 selects (ntile, k-half)
    int jrow = ((lane >> 4) & 1) * 8 + (lane & 7);
    int jcol = ((lane >> 3) & 1) * 8;
    int qr = lane >> 2, qc = (lane & 3) * 2;
    int m0 = wid * 16;

    for (int tile = blockIdx.x; tile < NTILE; tile += GRID) {
        int n0t  = tile * 128;
        int tok0 = n0t + m0 + qr;
        // clamped x row pointers (future steps reuse last input step)
        int b0i = tok0 / TTOT, t0 = tok0 - b0i * TTOT;
        if (t0 > TIN - 1) t0 = TIN - 1;
        int tok1 = tok0 + 8;
        int b1i = tok1 / TTOT, t1 = tok1 - b1i * TTOT;
        if (t1 > TIN - 1) t1 = TIN - 1;
        const float* xr0 = x + ((size_t)b0i * TIN + t0) * 32 + qc;
        const float* xr1 = x + ((size_t)b1i * TIN + t1) * 32 + qc;

        // A fragments for X: [kstep][a0..a3], fp16 hi + lo
        uint32_t axh[2][4], axl[2][4];
        #pragma unroll
        for (int ks = 0; ks < 2; ks++) {
            float2 f0 = *(const float2*)(xr0 + ks * 16);
            float2 f1 = *(const float2*)(xr1 + ks * 16);
            float2 f2 = *(const float2*)(xr0 + ks * 16 + 8);
            float2 f3 = *(const float2*)(xr1 + ks * 16 + 8);
            hsplit(f0.x, f0.y, axh[ks][0], axl[ks][0]);
            hsplit(f1.x, f1.y, axh[ks][1], axl[ks][1]);
            hsplit(f2.x, f2.y, axh[ks][2], axl[ks][2]);
            hsplit(f3.x, f3.y, axh[ks][3], axl[ks][3]);
        }

        float dacc[16];
        #pragma unroll
        for (int i = 0; i < 16; i++) dacc[i] = 0.0f;

        #pragma unroll 1
        for (int c = 0; c < 4; c++) {         // 64-hj chunks
            float aI[32], aG[32], aO[32];
            #pragma unroll
            for (int i = 0; i < 32; i++) { aI[i] = 0.f; aG[i] = 0.f; aO[i] = 0.f; }

            #pragma unroll
            for (int g3 = 0; g3 < 3; g3++) {
                float* acc = (g3 == 0) ? aI : (g3 == 1 ? aG : aO);
                int colb = g3 * 256 + c * 64;
                #pragma unroll
                for (int ntp = 0; ntp < 4; ntp++) {
                    int nw = colb + ntp * 16;
                    #pragma unroll
                    for (int ks = 0; ks < 2; ks++) {
                        uint32_t adr = sb + WG_H +
                            (uint32_t)((nw + jrow) * 40 + ks * 16 + jcol) * 2;
                        uint32_t bh0, bh1, bh2, bh3, bl0, bl1, bl2, bl3;
                        ldsm4(bh0, bh1, bh2, bh3, adr);
                        ldsm4(bl0, bl1, bl2, bl3, adr + (WG_L - WG_H));
                        float* A0 = acc + ntp * 8;
                        float* A1 = acc + ntp * 8 + 4;
                        mma16816(A0, axh[ks][0], axh[ks][1], axh[ks][2], axh[ks][3], bh0, bh1);
                        mma16816(A1, axh[ks][0], axh[ks][1], axh[ks][2], axh[ks][3], bh2, bh3);
                        mma16816(A0, axl[ks][0], axl[ks][1], axl[ks][2], axl[ks][3], bh0, bh1);
                        mma16816(A1, axl[ks][0], axl[ks][1], axl[ks][2], axl[ks][3], bh2, bh3);
                        mma16816(A0, axh[ks][0], axh[ks][1], axh[ks][2], axh[ks][3], bl0, bl1);
                        mma16816(A1, axh[ks][0], axh[ks][1], axh[ks][2], axh[ks][3], bl2, bl3);
                    }
                }
            }

            // activation -> h fragments (hi/lo), already in decoder-A layout
            uint32_t hh[16], hl[16];
            #pragma unroll
            for (int nt = 0; nt < 8; nt++) {
                int col = c * 64 + nt * 8 + qc;
                float2 bi = *(const float2*)&bias_s[col];
                float2 bg = *(const float2*)&bias_s[256 + col];
                float2 bo = *(const float2*)&bias_s[512 + col];
                int q = nt * 4;
                float h0 = actf(aI[q]     + bi.x, aG[q]     + bg.x, aO[q]     + bo.x);
                float h1 = actf(aI[q + 1] + bi.y, aG[q + 1] + bg.y, aO[q + 1] + bo.y);
                float h2 = actf(aI[q + 2] + bi.x, aG[q + 2] + bg.x, aO[q + 2] + bo.x);
                float h3 = actf(aI[q + 3] + bi.y, aG[q + 3] + bg.y, aO[q + 3] + bo.y);
                hsplit(h0, h1, hh[nt * 2],     hl[nt * 2]);
                hsplit(h2, h3, hh[nt * 2 + 1], hl[nt * 2 + 1]);
            }

            // decoder partial over this chunk's 64 k (h) values
            #pragma unroll
            for (int ks = 0; ks < 4; ks++) {
                uint32_t a0h = hh[4 * ks], a1h = hh[4 * ks + 1];
                uint32_t a2h = hh[4 * ks + 2], a3h = hh[4 * ks + 3];
                uint32_t a0l = hl[4 * ks], a1l = hl[4 * ks + 1];
                uint32_t a2l = hl[4 * ks + 2], a3l = hl[4 * ks + 3];
                #pragma unroll
                for (int otp = 0; otp < 2; otp++) {
                    uint32_t adr = sb + DW_H +
                        (uint32_t)((c * 32 + otp * 16 + jrow) * 72 + ks * 16 + jcol) * 2;
                    uint32_t bh0, bh1, bh2, bh3, bl0, bl1, bl2, bl3;
                    ldsm4(bh0, bh1, bh2, bh3, adr);
                    ldsm4(bl0, bl1, bl2, bl3, adr + (DW_L - DW_H));
                    float* D0 = dacc + otp * 8;
                    float* D1 = dacc + otp * 8 + 4;
                    mma16816(D0, a0h, a1h, a2h, a3h, bh0, bh1);
                    mma16816(D1, a0h, a1h, a2h, a3h, bh2, bh3);
                    mma16816(D0, a0l, a1l, a2l, a3l, bh0, bh1);
                    mma16816(D1, a0l, a1l, a2l, a3l, bh2, bh3);
                    mma16816(D0, a0h, a1h, a2h, a3h, bl0, bl1);
                    mma16816(D1, a0h, a1h, a2h, a3h, bl2, bl3);
                }
            }
        }

        // epilogue: out = dacc + dec_b (tok indices unclamped)
        #pragma unroll
        for (int ot = 0; ot < 4; ot++) {
            int col = ot * 8 + qc;
            float2 db = *(const float2*)&decb_s[col];
            float2 r0, r1;
            r0.x = dacc[ot * 4]     + db.x;  r0.y = dacc[ot * 4 + 1] + db.y;
            r1.x = dacc[ot * 4 + 2] + db.x;  r1.y = dacc[ot * 4 + 3] + db.y;
            *(float2*)&out[(size_t)tok0 * 32 + col]       = r0;
            *(float2*)&out[(size_t)(tok0 + 8) * 32 + col] = r1;
        }
    }
}

// ---------------------------------------------------------------------------
// Inputs (metadata order): input_seq, enc_W, enc_b, W_ih, W_hh, b_ih, b_hh,
//                          dec_W, dec_b, future_n
// W_hh is dead (state never updates from zeros); future_n fixed at 64.
// ---------------------------------------------------------------------------
extern "C" void kernel_launch(void* const* d_in, const int* in_sizes, int n_in,
                              void* d_out, int out_size) {
    (void)in_sizes; (void)n_in; (void)out_size;
    const float* input = (const float*)d_in[0];
    const float* encW  = (const float*)d_in[1];
    const float* encb  = (const float*)d_in[2];
    const float* Wih   = (const float*)d_in[3];
    const float* bih   = (const float*)d_in[5];
    const float* bhh   = (const float*)d_in[6];
    const float* decW  = (const float*)d_in[7];
    const float* decb  = (const float*)d_in[8];
    float* out = (float*)d_out;

    cudaFuncSetAttribute(fused_kernel,
                         cudaFuncAttributeMaxDynamicSharedMemorySize, SMEM_TOTAL);

    prep_kernel<<<824, 32>>>(Wih, encW, encb, bih, bhh, decW);
    fused_kernel<<<GRID, 256, SMEM_TOTAL>>>(input, decb, out);
}

// round 9
// speedup vs baseline: 2.9696x; 1.5669x over previous
#include <cuda_runtime.h>
#include <cuda_fp16.h>
#include <cstdint>
#include <cstring>

// Problem constants (fixed shapes):
//   B=128, T=2048, F_IN=32, R=256, H=256, F_OUT=32, future_n=64
//   total tokens N = 128 * (2048+64) = 270336
#define NTOTAL 270336
#define TTOT   2112
#define TIN    2048
#define NTILE  1056          // 256-token tiles
#define GRID   148

// Fused-weight fp16 hi/lo images (gmem, written by prep):
//   Wg: [768 gate-cols (i:0-255, g:256-511, o:512-767)][32 k]
//   dW: [32 o][256 k]
__device__ unsigned short g_WgH[768 * 32];
__device__ unsigned short g_WgL[768 * 32];
__device__ unsigned short g_dWH[32 * 256];
__device__ unsigned short g_dWL[32 * 256];
__device__ float g_bias[768];

// ---- SMEM layout (bytes). Wg rows padded to 40 halfs (80B, conflict-free
// for ldmatrix); dW stored k-chunked [4][32 o][64k pad 72]. ----
#define WG_H     0            // 768*40*2 = 61440
#define WG_L     61440
#define DW_H     122880       // 128*72*2 = 18432
#define DW_L     141312
#define BIAS_OFF 159744       // 768 f32
#define DECB_OFF 162816       // 32 f32
#define SMEM_TOTAL 162944

__device__ __forceinline__ uint32_t smem_u32(const void* p) {
    uint32_t a;
    asm("{ .reg .u64 t; cvta.to.shared.u64 t, %1; cvt.u32.u64 %0, t; }"
        : "=r"(a) : "l"(p));
    return a;
}
__device__ __forceinline__ void ldsm4(uint32_t& r0, uint32_t& r1,
                                      uint32_t& r2, uint32_t& r3, uint32_t a) {
    asm volatile("ldmatrix.sync.aligned.m8n8.x4.shared.b16 {%0,%1,%2,%3}, [%4];"
                 : "=r"(r0), "=r"(r1), "=r"(r2), "=r"(r3) : "r"(a));
}
__device__ __forceinline__ void mma16816(float* d,
                                         uint32_t a0, uint32_t a1,
                                         uint32_t a2, uint32_t a3,
                                         uint32_t b0, uint32_t b1) {
    asm volatile(
        "mma.sync.aligned.m16n8k16.row.col.f32.f16.f16.f32 "
        "{%0,%1,%2,%3}, {%4,%5,%6,%7}, {%8,%9}, {%0,%1,%2,%3};"
        : "+f"(d[0]), "+f"(d[1]), "+f"(d[2]), "+f"(d[3])
        : "r"(a0), "r"(a1), "r"(a2), "r"(a3), "r"(b0), "r"(b1));
}
// MUFU.TANH activations (validated rel_err ~5e-6)
__device__ __forceinline__ float tanh_a(float v) {
    float r; asm("tanh.approx.f32 %0, %1;" : "=f"(r) : "f"(v)); return r;
}
__device__ __forceinline__ float sig_a(float v) {
    return fmaf(0.5f, tanh_a(0.5f * v), 0.5f);
}
__device__ __forceinline__ float actf(float iv, float gv, float ov) {
    float cc = sig_a(iv) * tanh_a(gv);
    return sig_a(ov) * tanh_a(cc);
}
// fp16 hi/lo split of a float pair -> packed f16x2 regs (lo-half = first arg)
__device__ __forceinline__ void hsplit(float a, float b,
                                       uint32_t& hi, uint32_t& lo) {
    __half2 h = __floats2half2_rn(a, b);
    float2 bk = __half22float2(h);
    __half2 l = __floats2half2_rn(a - bk.x, b - bk.y);
    memcpy(&hi, &h, 4);
    memcpy(&lo, &l, 4);
}

// ---------------------------------------------------------------------------
// K1: fold encoder into LSTM input weights -> fp16 hi/lo images.
//   bid <  768 : fused M row (one k per lane)
//   768..791   : fused biases
//   792..823   : dec_W row (o = bid-792)
// ---------------------------------------------------------------------------
__global__ void prep_kernel(const float* __restrict__ Wih,
                            const float* __restrict__ encW,
                            const float* __restrict__ encb,
                            const float* __restrict__ bih,
                            const float* __restrict__ bhh,
                            const float* __restrict__ decW) {
    __shared__ float wr_s[256];
    int bid = blockIdx.x, lane = threadIdx.x;
    if (bid < 768) {
        int p  = bid >> 8;
        int hj = bid & 255;
        int row = hj + (p == 0 ? 0 : (p == 1 ? 512 : 768));
        const float* wr = Wih + row * 256;
        #pragma unroll
        for (int i = 0; i < 8; i++) wr_s[lane + 32 * i] = wr[lane + 32 * i];
        __syncwarp();
        float s = 0.0f;
        #pragma unroll 8
        for (int r = 0; r < 256; r++) s += wr_s[r] * encW[r * 32 + lane];
        __half hi = __float2half_rn(s);
        __half lo = __float2half_rn(s - __half2float(hi));
        int idx = bid * 32 + lane;          // col*32 + k
        g_WgH[idx] = *(unsigned short*)&hi;
        g_WgL[idx] = *(unsigned short*)&lo;
    } else if (bid < 792) {
        int q = (bid - 768) * 32 + lane;    // 0..767
        int p  = q >> 8;
        int hj = q & 255;
        int row = hj + (p == 0 ? 0 : (p == 1 ? 512 : 768));
        const float* wr = Wih + row * 256;
        float s = 0.0f;
        #pragma unroll 8
        for (int r = 0; r < 256; r++) s += wr[r] * encb[r];
        g_bias[p * 256 + hj] = s + bih[row] + bhh[row];
    } else {
        int o = bid - 792;                  // 0..31
        #pragma unroll
        for (int i = 0; i < 8; i++) {
            int k = lane + 32 * i;
            float v = decW[o * 256 + k];
            __half hi = __float2half_rn(v);
            __half lo = __float2half_rn(v - __half2float(hi));
            g_dWH[o * 256 + k] = *(unsigned short*)&hi;
            g_dWL[o * 256 + k] = *(unsigned short*)&lo;
        }
    }
}

// ---------------------------------------------------------------------------
// K2: persistent fused kernel. 148 CTAs x 512 threads (16 warps), 1 CTA/SM.
// Each warp owns 16 tokens of a 256-token tile, end-to-end, no tile barriers:
//   x (gmem f32 -> reg fp16 hi/lo A-frags)
//   per 32-col chunk (8 chunks): gates MMA (3-term fp16 split) -> activation
//     in regs -> h repacked as decoder A-frags (same lane layout) -> dec MMA
//   epilogue: dacc + dec_b -> STG.
// Chunk=32 keeps regs <=128 so 16 warps fit the RF (occ 25%, 4 warps/SMSP).
// ---------------------------------------------------------------------------
__global__ __launch_bounds__(512)
void fused_kernel(const float* __restrict__ x,
                  const float* __restrict__ decb,
                  float* __restrict__ out) {
    extern __shared__ char smem[];
    int tid = threadIdx.x, wid = tid >> 5, lane = tid & 31;

    // ---- stage split weights into padded smem ----
    {
        unsigned short* wgH = (unsigned short*)(smem + WG_H);
        unsigned short* wgL = (unsigned short*)(smem + WG_L);
        for (int i = tid; i < 24576; i += 512) {
            int col = i >> 5, k = i & 31;
            wgH[col * 40 + k] = g_WgH[i];
            wgL[col * 40 + k] = g_WgL[i];
        }
        unsigned short* dwH = (unsigned short*)(smem + DW_H);
        unsigned short* dwL = (unsigned short*)(smem + DW_L);
        for (int i = tid; i < 8192; i += 512) {
            int o = i >> 8, k = i & 255;
            int row = (k >> 6) * 32 + o, ck = k & 63;
            dwH[row * 72 + ck] = g_dWH[i];
            dwL[row * 72 + ck] = g_dWL[i];
        }
        float* bs = (float*)(smem + BIAS_OFF);
        for (int i = tid; i < 768; i += 512) bs[i] = g_bias[i];
        if (tid < 32) ((float*)(smem + DECB_OFF))[tid] = decb[tid];
    }
    __syncthreads();

    uint32_t sb = smem_u32(smem);
    const float* bias_s = (const float*)(smem + BIAS_OFF);
    const float* decb_s = (const float*)(smem + DECB_OFF);

    // ldmatrix lane geometry: j = lane/8 selects (ntile, k-half)
    int jrow = ((lane >> 4) & 1) * 8 + (lane & 7);
    int jcol = ((lane >> 3) & 1) * 8;
    int qr = lane >> 2, qc = (lane & 3) * 2;
    int m0 = wid * 16;

    for (int tile = blockIdx.x; tile < NTILE; tile += GRID) {
        int n0t  = tile * 256;
        int tok0 = n0t + m0 + qr;
        // clamped x row pointers (future steps reuse last input step)
        int b0i = tok0 / TTOT, t0 = tok0 - b0i * TTOT;
        if (t0 > TIN - 1) t0 = TIN - 1;
        int tok1 = tok0 + 8;
        int b1i = tok1 / TTOT, t1 = tok1 - b1i * TTOT;
        if (t1 > TIN - 1) t1 = TIN - 1;
        const float* xr0 = x + ((size_t)b0i * TIN + t0) * 32 + qc;
        const float* xr1 = x + ((size_t)b1i * TIN + t1) * 32 + qc;

        // A fragments for X: [kstep][a0..a3], fp16 hi + lo
        uint32_t axh[2][4], axl[2][4];
        #pragma unroll
        for (int ks = 0; ks < 2; ks++) {
            float2 f0 = *(const float2*)(xr0 + ks * 16);
            float2 f1 = *(const float2*)(xr1 + ks * 16);
            float2 f2 = *(const float2*)(xr0 + ks * 16 + 8);
            float2 f3 = *(const float2*)(xr1 + ks * 16 + 8);
            hsplit(f0.x, f0.y, axh[ks][0], axl[ks][0]);
            hsplit(f1.x, f1.y, axh[ks][1], axl[ks][1]);
            hsplit(f2.x, f2.y, axh[ks][2], axl[ks][2]);
            hsplit(f3.x, f3.y, axh[ks][3], axl[ks][3]);
        }

        float dacc[16];
        #pragma unroll
        for (int i = 0; i < 16; i++) dacc[i] = 0.0f;

        #pragma unroll 1
        for (int c = 0; c < 8; c++) {         // 32-hj chunks
            float aI[16], aG[16], aO[16];
            #pragma unroll
            for (int i = 0; i < 16; i++) { aI[i] = 0.f; aG[i] = 0.f; aO[i] = 0.f; }

            #pragma unroll
            for (int g3 = 0; g3 < 3; g3++) {
                float* acc = (g3 == 0) ? aI : (g3 == 1 ? aG : aO);
                int colb = g3 * 256 + c * 32;
                #pragma unroll
                for (int ntp = 0; ntp < 2; ntp++) {
                    int nw = colb + ntp * 16;
                    #pragma unroll
                    for (int ks = 0; ks < 2; ks++) {
                        uint32_t adr = sb + WG_H +
                            (uint32_t)((nw + jrow) * 40 + ks * 16 + jcol) * 2;
                        uint32_t bh0, bh1, bh2, bh3, bl0, bl1, bl2, bl3;
                        ldsm4(bh0, bh1, bh2, bh3, adr);
                        ldsm4(bl0, bl1, bl2, bl3, adr + (WG_L - WG_H));
                        float* A0 = acc + ntp * 8;
                        float* A1 = acc + ntp * 8 + 4;
                        mma16816(A0, axh[ks][0], axh[ks][1], axh[ks][2], axh[ks][3], bh0, bh1);
                        mma16816(A1, axh[ks][0], axh[ks][1], axh[ks][2], axh[ks][3], bh2, bh3);
                        mma16816(A0, axl[ks][0], axl[ks][1], axl[ks][2], axl[ks][3], bh0, bh1);
                        mma16816(A1, axl[ks][0], axl[ks][1], axl[ks][2], axl[ks][3], bh2, bh3);
                        mma16816(A0, axh[ks][0], axh[ks][1], axh[ks][2], axh[ks][3], bl0, bl1);
                        mma16816(A1, axh[ks][0], axh[ks][1], axh[ks][2], axh[ks][3], bl2, bl3);
                    }
                }
            }

            // activation -> h fragments (hi/lo), already in decoder-A layout
            uint32_t hh[8], hl[8];
            #pragma unroll
            for (int nt = 0; nt < 4; nt++) {
                int col = c * 32 + nt * 8 + qc;
                float2 bi = *(const float2*)&bias_s[col];
                float2 bg = *(const float2*)&bias_s[256 + col];
                float2 bo = *(const float2*)&bias_s[512 + col];
                int q = nt * 4;
                float h0 = actf(aI[q]     + bi.x, aG[q]     + bg.x, aO[q]     + bo.x);
                float h1 = actf(aI[q + 1] + bi.y, aG[q + 1] + bg.y, aO[q + 1] + bo.y);
                float h2 = actf(aI[q + 2] + bi.x, aG[q + 2] + bg.x, aO[q + 2] + bo.x);
                float h3 = actf(aI[q + 3] + bi.y, aG[q + 3] + bg.y, aO[q + 3] + bo.y);
                hsplit(h0, h1, hh[nt * 2],     hl[nt * 2]);
                hsplit(h2, h3, hh[nt * 2 + 1], hl[nt * 2 + 1]);
            }

            // decoder partial over this chunk's 32 k (h) values
            #pragma unroll
            for (int ks = 0; ks < 2; ks++) {
                int gk = c * 32 + ks * 16;             // global k
                int kc = gk >> 6, ck = gk & 63;
                uint32_t a0h = hh[4 * ks], a1h = hh[4 * ks + 1];
                uint32_t a2h = hh[4 * ks + 2], a3h = hh[4 * ks + 3];
                uint32_t a0l = hl[4 * ks], a1l = hl[4 * ks + 1];
                uint32_t a2l = hl[4 * ks + 2], a3l = hl[4 * ks + 3];
                #pragma unroll
                for (int otp = 0; otp < 2; otp++) {
                    uint32_t adr = sb + DW_H +
                        (uint32_t)((kc * 32 + otp * 16 + jrow) * 72 + ck + jcol) * 2;
                    uint32_t bh0, bh1, bh2, bh3, bl0, bl1, bl2, bl3;
                    ldsm4(bh0, bh1, bh2, bh3, adr);
                    ldsm4(bl0, bl1, bl2, bl3, adr + (DW_L - DW_H));
                    float* D0 = dacc + otp * 8;
                    float* D1 = dacc + otp * 8 + 4;
                    mma16816(D0, a0h, a1h, a2h, a3h, bh0, bh1);
                    mma16816(D1, a0h, a1h, a2h, a3h, bh2, bh3);
                    mma16816(D0, a0l, a1l, a2l, a3l, bh0, bh1);
                    mma16816(D1, a0l, a1l, a2l, a3l, bh2, bh3);
                    mma16816(D0, a0h, a1h, a2h, a3h, bl0, bl1);
                    mma16816(D1, a0h, a1h, a2h, a3h, bl2, bl3);
                }
            }
        }

        // epilogue: out = dacc + dec_b
        #pragma unroll
        for (int ot = 0; ot < 4; ot++) {
            int col = ot * 8 + qc;
            float2 db = *(const float2*)&decb_s[col];
            float2 r0, r1;
            r0.x = dacc[ot * 4]     + db.x;  r0.y = dacc[ot * 4 + 1] + db.y;
            r1.x = dacc[ot * 4 + 2] + db.x;  r1.y = dacc[ot * 4 + 3] + db.y;
            *(float2*)&out[(size_t)tok0 * 32 + col]       = r0;
            *(float2*)&out[(size_t)(tok0 + 8) * 32 + col] = r1;
        }
    }
}

// ---------------------------------------------------------------------------
// Inputs (metadata order): input_seq, enc_W, enc_b, W_ih, W_hh, b_ih, b_hh,
//                          dec_W, dec_b, future_n
// W_hh is dead (state never updates from zeros); future_n fixed at 64.
// ---------------------------------------------------------------------------
extern "C" void kernel_launch(void* const* d_in, const int* in_sizes, int n_in,
                              void* d_out, int out_size) {
    (void)in_sizes; (void)n_in; (void)out_size;
    const float* input = (const float*)d_in[0];
    const float* encW  = (const float*)d_in[1];
    const float* encb  = (const float*)d_in[2];
    const float* Wih   = (const float*)d_in[3];
    const float* bih   = (const float*)d_in[5];
    const float* bhh   = (const float*)d_in[6];
    const float* decW  = (const float*)d_in[7];
    const float* decb  = (const float*)d_in[8];
    float* out = (float*)d_out;

    cudaFuncSetAttribute(fused_kernel,
                         cudaFuncAttributeMaxDynamicSharedMemorySize, SMEM_TOTAL);

    prep_kernel<<<824, 32>>>(Wih, encW, encb, bih, bhh, decW);
    fused_kernel<<<GRID, 512, SMEM_TOTAL>>>(input, decb, out);
}

// round 10
// speedup vs baseline: 3.1751x; 1.0692x over previous
#include <cuda_runtime.h>
#include <cuda_fp16.h>
#include <cstdint>
#include <cstring>

// Problem constants (fixed shapes):
//   B=128, T=2048, F_IN=32, R=256, H=256, F_OUT=32, future_n=64
//   total tokens N = 128 * (2048+64) = 270336
#define NTOTAL 270336
#define TTOT   2112
#define TIN    2048
#define NTILE  704           // 384-token tiles (24 warps x 16 tokens)
#define GRID   148

// Fused-weight fp16 hi/lo images (gmem, written by prep):
//   Wg: [768 gate-cols (i:0-255, g:256-511, o:512-767)][32 k]
//   dW: [32 o][256 k]
__device__ unsigned short g_WgH[768 * 32];
__device__ unsigned short g_WgL[768 * 32];
__device__ unsigned short g_dWH[32 * 256];
__device__ unsigned short g_dWL[32 * 256];
__device__ float g_bias[768];

// ---- SMEM layout (bytes). Wg rows padded to 40 halfs (80B, conflict-free
// for ldmatrix); dW stored k-chunked [4][32 o][64k pad 72]. ----
#define WG_H     0            // 768*40*2 = 61440
#define WG_L     61440
#define DW_H     122880       // 128*72*2 = 18432
#define DW_L     141312
#define BIAS_OFF 159744       // 768 f32
#define DECB_OFF 162816       // 32 f32
#define SMEM_TOTAL 162944

__device__ __forceinline__ uint32_t smem_u32(const void* p) {
    uint32_t a;
    asm("{ .reg .u64 t; cvta.to.shared.u64 t, %1; cvt.u32.u64 %0, t; }"
        : "=r"(a) : "l"(p));
    return a;
}
__device__ __forceinline__ void ldsm4(uint32_t& r0, uint32_t& r1,
                                      uint32_t& r2, uint32_t& r3, uint32_t a) {
    asm volatile("ldmatrix.sync.aligned.m8n8.x4.shared.b16 {%0,%1,%2,%3}, [%4];"
                 : "=r"(r0), "=r"(r1), "=r"(r2), "=r"(r3) : "r"(a));
}
__device__ __forceinline__ void mma16816(float* d,
                                         uint32_t a0, uint32_t a1,
                                         uint32_t a2, uint32_t a3,
                                         uint32_t b0, uint32_t b1) {
    asm volatile(
        "mma.sync.aligned.m16n8k16.row.col.f32.f16.f16.f32 "
        "{%0,%1,%2,%3}, {%4,%5,%6,%7}, {%8,%9}, {%0,%1,%2,%3};"
        : "+f"(d[0]), "+f"(d[1]), "+f"(d[2]), "+f"(d[3])
        : "r"(a0), "r"(a1), "r"(a2), "r"(a3), "r"(b0), "r"(b1));
}
// MUFU.TANH activations (validated rel_err ~5e-6)
__device__ __forceinline__ float tanh_a(float v) {
    float r; asm("tanh.approx.f32 %0, %1;" : "=f"(r) : "f"(v)); return r;
}
__device__ __forceinline__ float sig_a(float v) {
    return fmaf(0.5f, tanh_a(0.5f * v), 0.5f);
}
__device__ __forceinline__ float actf(float iv, float gv, float ov) {
    float cc = sig_a(iv) * tanh_a(gv);
    return sig_a(ov) * tanh_a(cc);
}
// fp16 hi/lo split of a float pair -> packed f16x2 regs (lo-half = first arg)
__device__ __forceinline__ void hsplit(float a, float b,
                                       uint32_t& hi, uint32_t& lo) {
    __half2 h = __floats2half2_rn(a, b);
    float2 bk = __half22float2(h);
    __half2 l = __floats2half2_rn(a - bk.x, b - bk.y);
    memcpy(&hi, &h, 4);
    memcpy(&lo, &l, 4);
}

// ---------------------------------------------------------------------------
// K1: fold encoder into LSTM input weights -> fp16 hi/lo images.
//   bid <  768 : fused M row (one k per lane)
//   768..791   : fused biases
//   792..823   : dec_W row (o = bid-792)
// ---------------------------------------------------------------------------
__global__ void prep_kernel(const float* __restrict__ Wih,
                            const float* __restrict__ encW,
                            const float* __restrict__ encb,
                            const float* __restrict__ bih,
                            const float* __restrict__ bhh,
                            const float* __restrict__ decW) {
    __shared__ float wr_s[256];
    int bid = blockIdx.x, lane = threadIdx.x;
    if (bid < 768) {
        int p  = bid >> 8;
        int hj = bid & 255;
        int row = hj + (p == 0 ? 0 : (p == 1 ? 512 : 768));
        const float* wr = Wih + row * 256;
        #pragma unroll
        for (int i = 0; i < 8; i++) wr_s[lane + 32 * i] = wr[lane + 32 * i];
        __syncwarp();
        float s = 0.0f;
        #pragma unroll 8
        for (int r = 0; r < 256; r++) s += wr_s[r] * encW[r * 32 + lane];
        __half hi = __float2half_rn(s);
        __half lo = __float2half_rn(s - __half2float(hi));
        int idx = bid * 32 + lane;          // col*32 + k
        g_WgH[idx] = *(unsigned short*)&hi;
        g_WgL[idx] = *(unsigned short*)&lo;
    } else if (bid < 792) {
        int q = (bid - 768) * 32 + lane;    // 0..767
        int p  = q >> 8;
        int hj = q & 255;
        int row = hj + (p == 0 ? 0 : (p == 1 ? 512 : 768));
        const float* wr = Wih + row * 256;
        float s = 0.0f;
        #pragma unroll 8
        for (int r = 0; r < 256; r++) s += wr[r] * encb[r];
        g_bias[p * 256 + hj] = s + bih[row] + bhh[row];
    } else {
        int o = bid - 792;                  // 0..31
        #pragma unroll
        for (int i = 0; i < 8; i++) {
            int k = lane + 32 * i;
            float v = decW[o * 256 + k];
            __half hi = __float2half_rn(v);
            __half lo = __float2half_rn(v - __half2float(hi));
            g_dWH[o * 256 + k] = *(unsigned short*)&hi;
            g_dWL[o * 256 + k] = *(unsigned short*)&lo;
        }
    }
}

// ---------------------------------------------------------------------------
// K2: persistent fused kernel. 148 CTAs x 768 threads (24 warps), 1 CTA/SM.
// Each warp owns 16 tokens of a 384-token tile, end-to-end, no tile barriers:
//   x (gmem f32 -> reg fp16 hi/lo A-frags)
//   per 32-col chunk (8 chunks): gates MMA (3-term fp16 split) -> activation
//     in regs -> h repacked as decoder A-frags (same lane layout) -> dec MMA
//   epilogue: dacc + dec_b -> STG.
// 24 warps = 6/SMSP: covers ldsm->mma latency that limited R9 (issue 37.5%).
// Reg cap 84 (64K/768) vs 88 used at 512T — ptxas must shave ~4.
// ---------------------------------------------------------------------------
__global__ __launch_bounds__(768)
void fused_kernel(const float* __restrict__ x,
                  const float* __restrict__ decb,
                  float* __restrict__ out) {
    extern __shared__ char smem[];
    int tid = threadIdx.x, wid = tid >> 5, lane = tid & 31;

    // ---- stage split weights into padded smem ----
    {
        unsigned short* wgH = (unsigned short*)(smem + WG_H);
        unsigned short* wgL = (unsigned short*)(smem + WG_L);
        for (int i = tid; i < 24576; i += 768) {
            int col = i >> 5, k = i & 31;
            wgH[col * 40 + k] = g_WgH[i];
            wgL[col * 40 + k] = g_WgL[i];
        }
        unsigned short* dwH = (unsigned short*)(smem + DW_H);
        unsigned short* dwL = (unsigned short*)(smem + DW_L);
        for (int i = tid; i < 8192; i += 768) {
            int o = i >> 8, k = i & 255;
            int row = (k >> 6) * 32 + o, ck = k & 63;
            dwH[row * 72 + ck] = g_dWH[i];
            dwL[row * 72 + ck] = g_dWL[i];
        }
        float* bs = (float*)(smem + BIAS_OFF);
        for (int i = tid; i < 768; i += 768) bs[i] = g_bias[i];
        if (tid < 32) ((float*)(smem + DECB_OFF))[tid] = decb[tid];
    }
    __syncthreads();

    uint32_t sb = smem_u32(smem);
    const float* bias_s = (const float*)(smem + BIAS_OFF);
    const float* decb_s = (const float*)(smem + DECB_OFF);

    // ldmatrix lane geometry: j = lane/8 selects (ntile, k-half)
    int jrow = ((lane >> 4) & 1) * 8 + (lane & 7);
    int jcol = ((lane >> 3) & 1) * 8;
    int qr = lane >> 2, qc = (lane & 3) * 2;
    int m0 = wid * 16;

    for (int tile = blockIdx.x; tile < NTILE; tile += GRID) {
        int n0t  = tile * 384;
        int tok0 = n0t + m0 + qr;
        // clamped x row pointers (future steps reuse last input step)
        int b0i = tok0 / TTOT, t0 = tok0 - b0i * TTOT;
        if (t0 > TIN - 1) t0 = TIN - 1;
        int tok1 = tok0 + 8;
        int b1i = tok1 / TTOT, t1 = tok1 - b1i * TTOT;
        if (t1 > TIN - 1) t1 = TIN - 1;
        const float* xr0 = x + ((size_t)b0i * TIN + t0) * 32 + qc;
        const float* xr1 = x + ((size_t)b1i * TIN + t1) * 32 + qc;

        // A fragments for X: [kstep][a0..a3], fp16 hi + lo
        uint32_t axh[2][4], axl[2][4];
        #pragma unroll
        for (int ks = 0; ks < 2; ks++) {
            float2 f0 = *(const float2*)(xr0 + ks * 16);
            float2 f1 = *(const float2*)(xr1 + ks * 16);
            float2 f2 = *(const float2*)(xr0 + ks * 16 + 8);
            float2 f3 = *(const float2*)(xr1 + ks * 16 + 8);
            hsplit(f0.x, f0.y, axh[ks][0], axl[ks][0]);
            hsplit(f1.x, f1.y, axh[ks][1], axl[ks][1]);
            hsplit(f2.x, f2.y, axh[ks][2], axl[ks][2]);
            hsplit(f3.x, f3.y, axh[ks][3], axl[ks][3]);
        }

        float dacc[16];
        #pragma unroll
        for (int i = 0; i < 16; i++) dacc[i] = 0.0f;

        #pragma unroll 1
        for (int c = 0; c < 8; c++) {         // 32-hj chunks
            float aI[16], aG[16], aO[16];
            #pragma unroll
            for (int i = 0; i < 16; i++) { aI[i] = 0.f; aG[i] = 0.f; aO[i] = 0.f; }

            #pragma unroll
            for (int g3 = 0; g3 < 3; g3++) {
                float* acc = (g3 == 0) ? aI : (g3 == 1 ? aG : aO);
                int colb = g3 * 256 + c * 32;
                #pragma unroll
                for (int ntp = 0; ntp < 2; ntp++) {
                    int nw = colb + ntp * 16;
                    #pragma unroll
                    for (int ks = 0; ks < 2; ks++) {
                        uint32_t adr = sb + WG_H +
                            (uint32_t)((nw + jrow) * 40 + ks * 16 + jcol) * 2;
                        uint32_t bh0, bh1, bh2, bh3, bl0, bl1, bl2, bl3;
                        ldsm4(bh0, bh1, bh2, bh3, adr);
                        ldsm4(bl0, bl1, bl2, bl3, adr + (WG_L - WG_H));
                        float* A0 = acc + ntp * 8;
                        float* A1 = acc + ntp * 8 + 4;
                        mma16816(A0, axh[ks][0], axh[ks][1], axh[ks][2], axh[ks][3], bh0, bh1);
                        mma16816(A1, axh[ks][0], axh[ks][1], axh[ks][2], axh[ks][3], bh2, bh3);
                        mma16816(A0, axl[ks][0], axl[ks][1], axl[ks][2], axl[ks][3], bh0, bh1);
                        mma16816(A1, axl[ks][0], axl[ks][1], axl[ks][2], axl[ks][3], bh2, bh3);
                        mma16816(A0, axh[ks][0], axh[ks][1], axh[ks][2], axh[ks][3], bl0, bl1);
                        mma16816(A1, axh[ks][0], axh[ks][1], axh[ks][2], axh[ks][3], bl2, bl3);
                    }
                }
            }

            // activation -> h fragments (hi/lo), already in decoder-A layout
            uint32_t hh[8], hl[8];
            #pragma unroll
            for (int nt = 0; nt < 4; nt++) {
                int col = c * 32 + nt * 8 + qc;
                float2 bi = *(const float2*)&bias_s[col];
                float2 bg = *(const float2*)&bias_s[256 + col];
                float2 bo = *(const float2*)&bias_s[512 + col];
                int q = nt * 4;
                float h0 = actf(aI[q]     + bi.x, aG[q]     + bg.x, aO[q]     + bo.x);
                float h1 = actf(aI[q + 1] + bi.y, aG[q + 1] + bg.y, aO[q + 1] + bo.y);
                float h2 = actf(aI[q + 2] + bi.x, aG[q + 2] + bg.x, aO[q + 2] + bo.x);
                float h3 = actf(aI[q + 3] + bi.y, aG[q + 3] + bg.y, aO[q + 3] + bo.y);
                hsplit(h0, h1, hh[nt * 2],     hl[nt * 2]);
                hsplit(h2, h3, hh[nt * 2 + 1], hl[nt * 2 + 1]);
            }

            // decoder partial over this chunk's 32 k (h) values
            #pragma unroll
            for (int ks = 0; ks < 2; ks++) {
                int gk = c * 32 + ks * 16;             // global k
                int kc = gk >> 6, ck = gk & 63;
                uint32_t a0h = hh[4 * ks], a1h = hh[4 * ks + 1];
                uint32_t a2h = hh[4 * ks + 2], a3h = hh[4 * ks + 3];
                uint32_t a0l = hl[4 * ks], a1l = hl[4 * ks + 1];
                uint32_t a2l = hl[4 * ks + 2], a3l = hl[4 * ks + 3];
                #pragma unroll
                for (int otp = 0; otp < 2; otp++) {
                    uint32_t adr = sb + DW_H +
                        (uint32_t)((kc * 32 + otp * 16 + jrow) * 72 + ck + jcol) * 2;
                    uint32_t bh0, bh1, bh2, bh3, bl0, bl1, bl2, bl3;
                    ldsm4(bh0, bh1, bh2, bh3, adr);
                    ldsm4(bl0, bl1, bl2, bl3, adr + (DW_L - DW_H));
                    float* D0 = dacc + otp * 8;
                    float* D1 = dacc + otp * 8 + 4;
                    mma16816(D0, a0h, a1h, a2h, a3h, bh0, bh1);
                    mma16816(D1, a0h, a1h, a2h, a3h, bh2, bh3);
                    mma16816(D0, a0l, a1l, a2l, a3l, bh0, bh1);
                    mma16816(D1, a0l, a1l, a2l, a3l, bh2, bh3);
                    mma16816(D0, a0h, a1h, a2h, a3h, bl0, bl1);
                    mma16816(D1, a0h, a1h, a2h, a3h, bl2, bl3);
                }
            }
        }

        // epilogue: out = dacc + dec_b
        #pragma unroll
        for (int ot = 0; ot < 4; ot++) {
            int col = ot * 8 + qc;
            float2 db = *(const float2*)&decb_s[col];
            float2 r0, r1;
            r0.x = dacc[ot * 4]     + db.x;  r0.y = dacc[ot * 4 + 1] + db.y;
            r1.x = dacc[ot * 4 + 2] + db.x;  r1.y = dacc[ot * 4 + 3] + db.y;
            *(float2*)&out[(size_t)tok0 * 32 + col]       = r0;
            *(float2*)&out[(size_t)(tok0 + 8) * 32 + col] = r1;
        }
    }
}

// ---------------------------------------------------------------------------
// Inputs (metadata order): input_seq, enc_W, enc_b, W_ih, W_hh, b_ih, b_hh,
//                          dec_W, dec_b, future_n
// W_hh is dead (state never updates from zeros); future_n fixed at 64.
// ---------------------------------------------------------------------------
extern "C" void kernel_launch(void* const* d_in, const int* in_sizes, int n_in,
                              void* d_out, int out_size) {
    (void)in_sizes; (void)n_in; (void)out_size;
    const float* input = (const float*)d_in[0];
    const float* encW  = (const float*)d_in[1];
    const float* encb  = (const float*)d_in[2];
    const float* Wih   = (const float*)d_in[3];
    const float* bih   = (const float*)d_in[5];
    const float* bhh   = (const float*)d_in[6];
    const float* decW  = (const float*)d_in[7];
    const float* decb  = (const float*)d_in[8];
    float* out = (float*)d_out;

    cudaFuncSetAttribute(fused_kernel,
                         cudaFuncAttributeMaxDynamicSharedMemorySize, SMEM_TOTAL);

    prep_kernel<<<824, 32>>>(Wih, encW, encb, bih, bhh, decW);
    fused_kernel<<<GRID, 768, SMEM_TOTAL>>>(input, decb, out);
}